// round 1
// baseline (speedup 1.0000x reference)
#include <cuda_runtime.h>

// Problem constants (fixed shapes for this problem)
#define NN  100000
#define EE  1600000
#define GG  128
#define HID 32
#define CIN 64

// -------- device scratch (static, no allocation) --------
__device__ int   g_degi[NN];          // in-degree (no self loop)
__device__ float g_dinv[NN];          // rsqrt(deg+1)
__device__ int   g_rowptr[NN];        // CSR row start (by dst)
__device__ int   g_cursor[NN];        // fill cursors
__device__ int   g_bsum[128];         // scan block sums
__device__ int   g_cnt[GG];           // nodes per group
__device__ int   g_col[EE];           // CSR column (src node)
__device__ float g_wsrc[EE];          // dinv[src] per CSR entry
__device__ float g_tmp[(size_t)NN * HID];  // h @ W
__device__ float g_h[(size_t)NN * HID];    // layer output
__device__ float g_pool[GG * HID];         // pooled sums (accumulated over layers)

// -------- init --------
__global__ void k_zero(int n) {
    int i = blockIdx.x * blockDim.x + threadIdx.x;
    if (i < n)        g_degi[i] = 0;
    if (i < GG)       g_cnt[i]  = 0;
    if (i < GG * HID) g_pool[i] = 0.0f;
}

__global__ void k_deg(const int* __restrict__ dst, int e) {
    int i = blockIdx.x * blockDim.x + threadIdx.x;
    if (i < e) atomicAdd(&g_degi[dst[i]], 1);
}

__global__ void k_cnt(const int* __restrict__ batch, int n) {
    int i = blockIdx.x * blockDim.x + threadIdx.x;
    if (i < n) atomicAdd(&g_cnt[batch[i]], 1);
}

// -------- exclusive scan of g_degi -> g_rowptr (3-phase) --------
__global__ void k_scan1(int n) {
    __shared__ int s[1024];
    int i = blockIdx.x * 1024 + threadIdx.x;
    int v = (i < n) ? g_degi[i] : 0;
    s[threadIdx.x] = v;
    __syncthreads();
#pragma unroll
    for (int off = 1; off < 1024; off <<= 1) {
        int t = (threadIdx.x >= off) ? s[threadIdx.x - off] : 0;
        __syncthreads();
        s[threadIdx.x] += t;
        __syncthreads();
    }
    if (i < n) {
        g_rowptr[i] = s[threadIdx.x] - v;              // exclusive
        g_dinv[i]   = rsqrtf((float)v + 1.0f);         // deg incl. self loop
    }
    if (threadIdx.x == 1023) g_bsum[blockIdx.x] = s[1023];
}

__global__ void k_scan2(int nb) {
    __shared__ int s[128];
    int v = (threadIdx.x < nb) ? g_bsum[threadIdx.x] : 0;
    s[threadIdx.x] = v;
    __syncthreads();
#pragma unroll
    for (int off = 1; off < 128; off <<= 1) {
        int t = (threadIdx.x >= off) ? s[threadIdx.x - off] : 0;
        __syncthreads();
        s[threadIdx.x] += t;
        __syncthreads();
    }
    g_bsum[threadIdx.x] = s[threadIdx.x] - v;          // exclusive
}

__global__ void k_scan3(int n) {
    int i = blockIdx.x * blockDim.x + threadIdx.x;
    if (i < n) {
        int r = g_rowptr[i] + g_bsum[i >> 10];
        g_rowptr[i] = r;
        g_cursor[i] = r;
    }
}

__global__ void k_fill(const int* __restrict__ src, const int* __restrict__ dst, int e) {
    int i = blockIdx.x * blockDim.x + threadIdx.x;
    if (i >= e) return;
    int s = src[i];
    int p = atomicAdd(&g_cursor[dst[i]], 1);
    g_col[p]  = s;
    g_wsrc[p] = g_dinv[s];
}

// -------- dense matmul: g_tmp = in[n,C] @ W[C,32]  --------
template <int C>
__global__ void k_mm(const float* __restrict__ in, const float* __restrict__ W, int n) {
    __shared__ float Ws[C * HID];
    for (int t = threadIdx.x; t < C * HID; t += blockDim.x) Ws[t] = W[t];
    __syncthreads();
    int row = blockIdx.x * blockDim.x + threadIdx.x;
    if (row >= n) return;

    float acc[HID];
#pragma unroll
    for (int c = 0; c < HID; c++) acc[c] = 0.0f;

    const float4* xr = reinterpret_cast<const float4*>(in) + (size_t)row * (C / 4);
    for (int k4 = 0; k4 < C / 4; k4++) {
        float4 xv = __ldg(&xr[k4]);
        float xs[4] = {xv.x, xv.y, xv.z, xv.w};
#pragma unroll
        for (int kk = 0; kk < 4; kk++) {
            const float4* wr = reinterpret_cast<const float4*>(Ws + (k4 * 4 + kk) * HID);
#pragma unroll
            for (int c4 = 0; c4 < HID / 4; c4++) {
                float4 w = wr[c4];
                acc[c4 * 4 + 0] = fmaf(xs[kk], w.x, acc[c4 * 4 + 0]);
                acc[c4 * 4 + 1] = fmaf(xs[kk], w.y, acc[c4 * 4 + 1]);
                acc[c4 * 4 + 2] = fmaf(xs[kk], w.z, acc[c4 * 4 + 2]);
                acc[c4 * 4 + 3] = fmaf(xs[kk], w.w, acc[c4 * 4 + 3]);
            }
        }
    }
    float4* o = reinterpret_cast<float4*>(g_tmp) + (size_t)row * (HID / 4);
#pragma unroll
    for (int c4 = 0; c4 < HID / 4; c4++)
        o[c4] = make_float4(acc[c4 * 4], acc[c4 * 4 + 1], acc[c4 * 4 + 2], acc[c4 * 4 + 3]);
}

// -------- fused aggregation + self-loop + bias + leaky-relu + pool --------
// one warp per node, lane = feature column
__global__ void k_agg(const float* __restrict__ bias, const int* __restrict__ batch, int n) {
    int w    = (blockIdx.x * blockDim.x + threadIdx.x) >> 5;
    int lane = threadIdx.x & 31;
    if (w >= n) return;

    int beg = g_rowptr[w];
    int cnt = g_degi[w];

    float acc = 0.0f;
    for (int base = 0; base < cnt; base += 32) {
        int m = cnt - base;
        if (m > 32) m = 32;
        int   cj = 0;
        float wj = 0.0f;
        if (lane < m) {
            cj = g_col[beg + base + lane];
            wj = g_wsrc[beg + base + lane];
        }
        for (int j = 0; j < m; j++) {
            int   c  = __shfl_sync(0xffffffffu, cj, j);
            float wv = __shfl_sync(0xffffffffu, wj, j);
            acc = fmaf(g_tmp[(size_t)c * HID + lane], wv, acc);
        }
    }

    float di  = g_dinv[w];
    float slf = g_tmp[(size_t)w * HID + lane] * di * di;
    float val = fmaf(acc, di, slf) + bias[lane];
    val = fmaxf(val, 0.01f * val);   // leaky relu

    g_h[(size_t)w * HID + lane] = val;
    atomicAdd(&g_pool[batch[w] * HID + lane], val);
}

// -------- finalize: mean over groups and over 3 layers --------
__global__ void k_fin(float* __restrict__ out) {
    int i = blockIdx.x * blockDim.x + threadIdx.x;
    if (i < GG * HID) {
        float c = (float)g_cnt[i >> 5];   // i / HID
        c = fmaxf(c, 1.0f);
        out[i] = g_pool[i] / (3.0f * c);
    }
}

extern "C" void kernel_launch(void* const* d_in, const int* in_sizes, int n_in,
                              void* d_out, int out_size) {
    const float* x     = (const float*)d_in[0];
    const float* W0    = (const float*)d_in[1];
    const float* b0    = (const float*)d_in[2];
    const float* W1    = (const float*)d_in[3];
    const float* b1    = (const float*)d_in[4];
    const float* W2    = (const float*)d_in[5];
    const float* b2    = (const float*)d_in[6];
    const int*   src   = (const int*)d_in[7];
    const int*   dst   = (const int*)d_in[8];
    const int*   batch = (const int*)d_in[9];
    float*       out   = (float*)d_out;

    int n = in_sizes[9];   // N (batch vector length)
    int e = in_sizes[7];   // E (src length)

    const int T = 256;

    // ---- preprocessing: degrees, counts, CSR by dst ----
    k_zero<<<(n + T - 1) / T, T>>>(n);
    k_deg <<<(e + T - 1) / T, T>>>(dst, e);
    k_cnt <<<(n + T - 1) / T, T>>>(batch, n);

    int nb = (n + 1023) / 1024;
    k_scan1<<<nb, 1024>>>(n);
    k_scan2<<<1, 128>>>(nb);
    k_scan3<<<(n + T - 1) / T, T>>>(n);
    k_fill <<<(e + T - 1) / T, T>>>(src, dst, e);

    void* hp = nullptr;
    cudaGetSymbolAddress(&hp, g_h);
    const float* h = (const float*)hp;

    int mmBlocks  = (n + 127) / 128;
    int aggBlocks = ((n * 32) + T - 1) / T;

    // ---- layer 0 ----
    k_mm<CIN><<<mmBlocks, 128>>>(x, W0, n);
    k_agg<<<aggBlocks, T>>>(b0, batch, n);
    // ---- layer 1 ----
    k_mm<HID><<<mmBlocks, 128>>>(h, W1, n);
    k_agg<<<aggBlocks, T>>>(b1, batch, n);
    // ---- layer 2 ----
    k_mm<HID><<<mmBlocks, 128>>>(h, W2, n);
    k_agg<<<aggBlocks, T>>>(b2, batch, n);

    // ---- finalize ----
    k_fin<<<(GG * HID + T - 1) / T, T>>>(out);
}

// round 2
// speedup vs baseline: 1.5592x; 1.5592x over previous
#include <cuda_runtime.h>

// Problem constants (fixed shapes)
#define NN  100000
#define EE  1600000
#define GG  128
#define HID 32
#define CIN 64

// -------- device scratch (static, no allocation) --------
__device__ int   g_degi[NN];               // in-degree (no self loop)
__device__ float g_dinv[NN];               // rsqrt(deg+1)
__device__ int   g_rowptr[NN];             // CSR row start (by dst)
__device__ int   g_cursor[NN];             // fill cursors
__device__ int   g_bsum[128];              // scan block sums
__device__ int   g_cnt[GG];                // nodes per group
__device__ int   g_col[EE];                // CSR column (src node)
__device__ float g_tmp[(size_t)NN * HID];  // (h @ W) * dinv[row]  (pre-scaled!)
__device__ float g_h[(size_t)NN * HID];    // layer output
__device__ float g_pool[GG * HID];         // pooled sums (all 3 layers)

// -------- init + histograms --------
__global__ void k_init(int n) {
    int i = blockIdx.x * blockDim.x + threadIdx.x;
    if (i < n)        g_degi[i] = 0;
    if (i < GG)       g_cnt[i]  = 0;
    if (i < GG * HID) g_pool[i] = 0.0f;
}

__global__ void k_count(const int* __restrict__ dst, const int* __restrict__ batch,
                        int e, int n) {
    int i = blockIdx.x * blockDim.x + threadIdx.x;
    if (i < e) atomicAdd(&g_degi[dst[i]], 1);
    if (i < n) atomicAdd(&g_cnt[batch[i]], 1);
}

// -------- exclusive scan of g_degi -> g_rowptr (warp-shuffle, 3-phase) --------
__global__ void k_scan1(int n) {
    __shared__ int wsum[32];
    int tid = threadIdx.x, lane = tid & 31, wid = tid >> 5;
    int i = blockIdx.x * 1024 + tid;
    int v = (i < n) ? g_degi[i] : 0;
    int s = v;
#pragma unroll
    for (int o = 1; o < 32; o <<= 1) {
        int t = __shfl_up_sync(0xffffffffu, s, o);
        if (lane >= o) s += t;
    }
    if (lane == 31) wsum[wid] = s;
    __syncthreads();
    if (wid == 0) {
        int ws = wsum[lane];
#pragma unroll
        for (int o = 1; o < 32; o <<= 1) {
            int t = __shfl_up_sync(0xffffffffu, ws, o);
            if (lane >= o) ws += t;
        }
        wsum[lane] = ws;
    }
    __syncthreads();
    int off = wid ? wsum[wid - 1] : 0;
    if (i < n) {
        g_rowptr[i] = off + s - v;               // exclusive
        g_dinv[i]   = rsqrtf((float)v + 1.0f);   // deg incl. self loop
    }
    if (tid == 1023) g_bsum[blockIdx.x] = wsum[31];
}

__global__ void k_scan2(int nb) {
    __shared__ int s[128];
    int v = (threadIdx.x < nb) ? g_bsum[threadIdx.x] : 0;
    s[threadIdx.x] = v;
    __syncthreads();
#pragma unroll
    for (int off = 1; off < 128; off <<= 1) {
        int t = (threadIdx.x >= off) ? s[threadIdx.x - off] : 0;
        __syncthreads();
        s[threadIdx.x] += t;
        __syncthreads();
    }
    g_bsum[threadIdx.x] = s[threadIdx.x] - v;    // exclusive
}

__global__ void k_scan3(int n) {
    int i = blockIdx.x * blockDim.x + threadIdx.x;
    if (i < n) {
        int r = g_rowptr[i] + g_bsum[i >> 10];
        g_rowptr[i] = r;
        g_cursor[i] = r;
    }
}

__global__ void k_fill(const int* __restrict__ src, const int* __restrict__ dst, int e) {
    int i = blockIdx.x * blockDim.x + threadIdx.x;
    if (i >= e) return;
    int s = src[i];
    int p = atomicAdd(&g_cursor[dst[i]], 1);
    g_col[p] = s;
}

// -------- dense matmul: g_tmp[row] = (in[row,:C] @ W[C,32]) * dinv[row] --------
// 4 rows x 16 cols per thread: W smem traffic = 1 byte/FMA
template <int C>
__global__ void __launch_bounds__(128) k_mm(const float* __restrict__ in,
                                            const float* __restrict__ W, int n) {
    __shared__ float Ws[C * HID];
    for (int t = threadIdx.x; t < C * HID; t += blockDim.x) Ws[t] = W[t];
    __syncthreads();

    int colh = threadIdx.x & 1;        // 16-column half
    int rg   = threadIdx.x >> 1;       // row group 0..63
    int row0 = blockIdx.x * 256 + rg * 4;

    float acc[4][16];
#pragma unroll
    for (int r = 0; r < 4; r++)
#pragma unroll
        for (int c = 0; c < 16; c++) acc[r][c] = 0.0f;

    for (int k4 = 0; k4 < C / 4; k4++) {
        float4 xv[4];
#pragma unroll
        for (int r = 0; r < 4; r++) {
            int row = row0 + r;
            xv[r] = (row < n)
                ? __ldg(reinterpret_cast<const float4*>(in) + (size_t)row * (C / 4) + k4)
                : make_float4(0.f, 0.f, 0.f, 0.f);
        }
#pragma unroll
        for (int kk = 0; kk < 4; kk++) {
            const float4* wr = reinterpret_cast<const float4*>(
                Ws + (k4 * 4 + kk) * HID + colh * 16);
            float4 w0 = wr[0], w1 = wr[1], w2 = wr[2], w3 = wr[3];
#pragma unroll
            for (int r = 0; r < 4; r++) {
                float xs = (kk == 0) ? xv[r].x : (kk == 1) ? xv[r].y
                         : (kk == 2) ? xv[r].z : xv[r].w;
                acc[r][0]  = fmaf(xs, w0.x, acc[r][0]);
                acc[r][1]  = fmaf(xs, w0.y, acc[r][1]);
                acc[r][2]  = fmaf(xs, w0.z, acc[r][2]);
                acc[r][3]  = fmaf(xs, w0.w, acc[r][3]);
                acc[r][4]  = fmaf(xs, w1.x, acc[r][4]);
                acc[r][5]  = fmaf(xs, w1.y, acc[r][5]);
                acc[r][6]  = fmaf(xs, w1.z, acc[r][6]);
                acc[r][7]  = fmaf(xs, w1.w, acc[r][7]);
                acc[r][8]  = fmaf(xs, w2.x, acc[r][8]);
                acc[r][9]  = fmaf(xs, w2.y, acc[r][9]);
                acc[r][10] = fmaf(xs, w2.z, acc[r][10]);
                acc[r][11] = fmaf(xs, w2.w, acc[r][11]);
                acc[r][12] = fmaf(xs, w3.x, acc[r][12]);
                acc[r][13] = fmaf(xs, w3.y, acc[r][13]);
                acc[r][14] = fmaf(xs, w3.z, acc[r][14]);
                acc[r][15] = fmaf(xs, w3.w, acc[r][15]);
            }
        }
    }

#pragma unroll
    for (int r = 0; r < 4; r++) {
        int row = row0 + r;
        if (row >= n) continue;
        float di = g_dinv[row];
        float4* o = reinterpret_cast<float4*>(g_tmp) + (size_t)row * 8 + colh * 4;
#pragma unroll
        for (int c4 = 0; c4 < 4; c4++)
            o[c4] = make_float4(acc[r][c4 * 4] * di, acc[r][c4 * 4 + 1] * di,
                                acc[r][c4 * 4 + 2] * di, acc[r][c4 * 4 + 3] * di);
    }
}

// -------- fused aggregation + self-loop + bias + leaky-relu + block pool --------
// warp = node; lane = (edge slot 0..3, feature quad 0..7); float4 per lane
__global__ void __launch_bounds__(256) k_agg(const float* __restrict__ bias,
                                             const int* __restrict__ batch,
                                             int n, int store_h) {
    __shared__ float sval[8][HID];
    __shared__ int   sgrp[8];

    int warp = threadIdx.x >> 5;       // 0..7 (node within block)
    int lane = threadIdx.x & 31;
    int w    = blockIdx.x * 8 + warp;
    int sub  = lane >> 3;              // edge slot 0..3
    int q    = lane & 7;               // feature quad 0..7
    int active = (w < n);

    int beg = 0, cnt = 0;
    if (active) { beg = g_rowptr[w]; cnt = g_degi[w]; }

    const float4* T4 = reinterpret_cast<const float4*>(g_tmp);
    float ax = 0.f, ay = 0.f, az = 0.f, aw = 0.f;

    for (int base = 0; base < cnt; base += 8) {
        int i0 = base + sub, i1 = base + 4 + sub;
        if (i0 < cnt) {
            int c = __ldg(&g_col[beg + i0]);
            float4 r = T4[(size_t)c * 8 + q];
            ax += r.x; ay += r.y; az += r.z; aw += r.w;
        }
        if (i1 < cnt) {
            int c = __ldg(&g_col[beg + i1]);
            float4 r = T4[(size_t)c * 8 + q];
            ax += r.x; ay += r.y; az += r.z; aw += r.w;
        }
    }

    // reduce across the 4 edge slots (stride 8 lanes)
#pragma unroll
    for (int o = 16; o >= 8; o >>= 1) {
        ax += __shfl_down_sync(0xffffffffu, ax, o);
        ay += __shfl_down_sync(0xffffffffu, ay, o);
        az += __shfl_down_sync(0xffffffffu, az, o);
        aw += __shfl_down_sync(0xffffffffu, aw, o);
    }

    if (active && lane < 8) {
        float4 self = T4[(size_t)w * 8 + lane];
        float  di   = g_dinv[w];
        float4 bb   = reinterpret_cast<const float4*>(bias)[lane];
        float4 v;
        v.x = (ax + self.x) * di + bb.x;
        v.y = (ay + self.y) * di + bb.y;
        v.z = (az + self.z) * di + bb.z;
        v.w = (aw + self.w) * di + bb.w;
        v.x = fmaxf(v.x, 0.01f * v.x);
        v.y = fmaxf(v.y, 0.01f * v.y);
        v.z = fmaxf(v.z, 0.01f * v.z);
        v.w = fmaxf(v.w, 0.01f * v.w);
        if (store_h)
            reinterpret_cast<float4*>(g_h)[(size_t)w * 8 + lane] = v;
        sval[warp][lane * 4 + 0] = v.x;
        sval[warp][lane * 4 + 1] = v.y;
        sval[warp][lane * 4 + 2] = v.z;
        sval[warp][lane * 4 + 3] = v.w;
    }
    if (lane == 0) sgrp[warp] = active ? batch[w] : -1;
    __syncthreads();

    // warp 0: segment-reduce 8 node vectors by group (batch is sorted),
    // then one atomicAdd per (group-run, feature)
    if (warp == 0) {
        float a = 0.f;
        int cur = sgrp[0];
#pragma unroll
        for (int nd = 0; nd < 8; nd++) {
            int g = sgrp[nd];
            if (g != cur) {
                if (cur >= 0) atomicAdd(&g_pool[cur * HID + lane], a);
                a = 0.f;
                cur = g;
            }
            if (g >= 0) a += sval[nd][lane];
        }
        if (cur >= 0) atomicAdd(&g_pool[cur * HID + lane], a);
    }
}

// -------- finalize: mean over groups and over 3 layers --------
__global__ void k_fin(float* __restrict__ out) {
    int i = blockIdx.x * blockDim.x + threadIdx.x;
    if (i < GG * HID) {
        float c = fmaxf((float)g_cnt[i >> 5], 1.0f);
        out[i] = g_pool[i] / (3.0f * c);
    }
}

extern "C" void kernel_launch(void* const* d_in, const int* in_sizes, int n_in,
                              void* d_out, int out_size) {
    const float* x     = (const float*)d_in[0];
    const float* W0    = (const float*)d_in[1];
    const float* b0    = (const float*)d_in[2];
    const float* W1    = (const float*)d_in[3];
    const float* b1    = (const float*)d_in[4];
    const float* W2    = (const float*)d_in[5];
    const float* b2    = (const float*)d_in[6];
    const int*   src   = (const int*)d_in[7];
    const int*   dst   = (const int*)d_in[8];
    const int*   batch = (const int*)d_in[9];
    float*       out   = (float*)d_out;

    int n = in_sizes[9];
    int e = in_sizes[7];
    const int T = 256;

    // ---- preprocessing ----
    k_init <<<(n + T - 1) / T, T>>>(n);
    int me = (e > n) ? e : n;
    k_count<<<(me + T - 1) / T, T>>>(dst, batch, e, n);

    int nb = (n + 1023) / 1024;
    k_scan1<<<nb, 1024>>>(n);
    k_scan2<<<1, 128>>>(nb);
    k_scan3<<<(n + T - 1) / T, T>>>(n);
    k_fill <<<(e + T - 1) / T, T>>>(src, dst, e);

    void* hp = nullptr;
    cudaGetSymbolAddress(&hp, g_h);
    const float* h = (const float*)hp;

    int mmBlocks  = (n + 255) / 256;
    int aggBlocks = (n + 7) / 8;

    // ---- layer 0 ----
    k_mm<CIN><<<mmBlocks, 128>>>(x, W0, n);
    k_agg<<<aggBlocks, 256>>>(b0, batch, n, 1);
    // ---- layer 1 ----
    k_mm<HID><<<mmBlocks, 128>>>(h, W1, n);
    k_agg<<<aggBlocks, 256>>>(b1, batch, n, 1);
    // ---- layer 2 ----
    k_mm<HID><<<mmBlocks, 128>>>(h, W2, n);
    k_agg<<<aggBlocks, 256>>>(b2, batch, n, 0);

    // ---- finalize ----
    k_fin<<<(GG * HID + T - 1) / T, T>>>(out);
}